// round 10
// baseline (speedup 1.0000x reference)
#include <cuda_runtime.h>
#include <cstdint>

// y[N] = x[N,H] @ w[H] + bias,  w[h] = FP4_TABLE[codes[h]] * absmax[h>>6]
// N = 32768, H = 4096.
//
// R9 conclusion: memory system is backpressure-bound at ~6.5TB/s; extra MLP
// is useless. Remaining loss is the partial final wave (4096 CTAs over 888
// resident slots, 18us CTA lifetime). R10: persistent CTAs (592 = 4/SM) with
// atomic row work-stealing -> perfectly balanced streaming, no wave tail.

#define H_DIM 4096
#define THREADS 256
#define GRID_CTAS 592                // 4 CTAs/SM * 148 SMs: one resident wave

__device__ float    g_w[H_DIM];      // dequantized weight scratch
__device__ unsigned g_row_ctr;       // work-stealing cursor (reset each replay)

__device__ __constant__ float c_fp4_tab[16] = {
    0.0f, 0.0052083333f, 0.6666667f, 1.0f, 0.3333333f, 0.5f, 0.16666667f, 0.25f,
    -0.0f, -0.0052083333f, -0.6666667f, -1.0f, -0.3333333f, -0.5f, -0.16666667f, -0.25f
};

__global__ void fp4_dequant_kernel(const int* __restrict__ codes,
                                   const float* __restrict__ absmax)
{
    int i = blockIdx.x * blockDim.x + threadIdx.x;
    if (i < H_DIM)
        g_w[i] = c_fp4_tab[codes[i] & 15] * absmax[i >> 6];
    if (i == 0)
        g_row_ctr = 0;               // deterministic across graph replays
}

__global__ __launch_bounds__(THREADS)
void fp4_gemv_kernel(const float* __restrict__ x,
                     const float* __restrict__ bias,
                     float*       __restrict__ y,
                     int N)
{
    const int lane = threadIdx.x & 31;
    const float4* __restrict__ wr = reinterpret_cast<const float4*>(g_w);
    const float b = __ldg(bias);

    for (;;) {
        // Lane 0 grabs the next row; broadcast to the warp.
        unsigned row;
        if (lane == 0) row = atomicAdd(&g_row_ctr, 1u);
        row = __shfl_sync(0xFFFFFFFFu, row, 0);
        if (row >= (unsigned)N) return;

        const float4* __restrict__ xr =
            reinterpret_cast<const float4*>(x + (size_t)row * H_DIM);

        // 1024 float4 per row; 32 per lane as 4 groups of 8 (R8 body).
        float acc0 = 0.0f, acc1 = 0.0f;
        #pragma unroll
        for (int g = 0; g < 4; g++) {
            float4 xv[8];
            #pragma unroll
            for (int j = 0; j < 8; j++) {
                xv[j] = __ldcs(&xr[g * 256 + j * 32 + lane]);  // read-once stream
            }
            #pragma unroll
            for (int j = 0; j < 8; j++) {
                float4 wv = __ldg(&wr[g * 256 + j * 32 + lane]); // L1-resident 16KB
                acc0 = fmaf(xv[j].x, wv.x, acc0);
                acc1 = fmaf(xv[j].y, wv.y, acc1);
                acc0 = fmaf(xv[j].z, wv.z, acc0);
                acc1 = fmaf(xv[j].w, wv.w, acc1);
            }
        }
        float acc = acc0 + acc1;

        #pragma unroll
        for (int off = 16; off > 0; off >>= 1)
            acc += __shfl_xor_sync(0xFFFFFFFFu, acc, off);

        if (lane == 0)
            y[row] = acc + b;
    }
}

extern "C" void kernel_launch(void* const* d_in, const int* in_sizes, int n_in,
                              void* d_out, int out_size)
{
    const float* x      = (const float*)d_in[0];   // [N, H] fp32
    const int*   codes  = (const int*)  d_in[1];   // [1, H] int32
    const float* absmax = (const float*)d_in[2];   // [1, H/64] fp32
    const float* bias   = (const float*)d_in[3];   // [1] fp32
    float*       y      = (float*)d_out;           // [N, 1] fp32

    const int N = in_sizes[0] / H_DIM;             // 32768

    fp4_dequant_kernel<<<(H_DIM + 255) / 256, 256>>>(codes, absmax);
    fp4_gemv_kernel<<<GRID_CTAS, THREADS>>>(x, bias, y, N);
}

// round 11
// speedup vs baseline: 1.0004x; 1.0004x over previous
#include <cuda_runtime.h>
#include <cstdint>

// y[N] = x[N,H] @ w[H] + bias,  w[h] = FP4_TABLE[codes[h]] * absmax[h>>6]
// N = 32768, H = 4096.
//
// R10 post-mortem: grid=592 capped residency at 4 CTAs/SM (50% occ) and
// bandwidth fell proportionally — achieved BW scales with resident warps here.
// R11: same persistent work-stealing kernel at FULL residency: 1184 CTAs
// (8/SM x 148 SMs, the regs=32/smem=0 limit), keeping tail elimination.

#define H_DIM 4096
#define THREADS 256
#define GRID_CTAS 1184               // 8 CTAs/SM * 148 SMs: full single wave

__device__ float    g_w[H_DIM];      // dequantized weight scratch
__device__ unsigned g_row_ctr;       // work-stealing cursor (reset each replay)

__device__ __constant__ float c_fp4_tab[16] = {
    0.0f, 0.0052083333f, 0.6666667f, 1.0f, 0.3333333f, 0.5f, 0.16666667f, 0.25f,
    -0.0f, -0.0052083333f, -0.6666667f, -1.0f, -0.3333333f, -0.5f, -0.16666667f, -0.25f
};

__global__ void fp4_dequant_kernel(const int* __restrict__ codes,
                                   const float* __restrict__ absmax)
{
    int i = blockIdx.x * blockDim.x + threadIdx.x;
    if (i < H_DIM)
        g_w[i] = c_fp4_tab[codes[i] & 15] * absmax[i >> 6];
    if (i == 0)
        g_row_ctr = 0;               // deterministic across graph replays
}

__global__ __launch_bounds__(THREADS)
void fp4_gemv_kernel(const float* __restrict__ x,
                     const float* __restrict__ bias,
                     float*       __restrict__ y,
                     int N)
{
    const int lane = threadIdx.x & 31;
    const float4* __restrict__ wr = reinterpret_cast<const float4*>(g_w);
    const float b = __ldg(bias);

    for (;;) {
        // Lane 0 grabs the next row; broadcast to the warp.
        unsigned row;
        if (lane == 0) row = atomicAdd(&g_row_ctr, 1u);
        row = __shfl_sync(0xFFFFFFFFu, row, 0);
        if (row >= (unsigned)N) return;

        const float4* __restrict__ xr =
            reinterpret_cast<const float4*>(x + (size_t)row * H_DIM);

        // 1024 float4 per row; 32 per lane as 4 groups of 8 (R8 body).
        float acc0 = 0.0f, acc1 = 0.0f;
        #pragma unroll
        for (int g = 0; g < 4; g++) {
            float4 xv[8];
            #pragma unroll
            for (int j = 0; j < 8; j++) {
                xv[j] = __ldcs(&xr[g * 256 + j * 32 + lane]);  // read-once stream
            }
            #pragma unroll
            for (int j = 0; j < 8; j++) {
                float4 wv = __ldg(&wr[g * 256 + j * 32 + lane]); // L1-resident 16KB
                acc0 = fmaf(xv[j].x, wv.x, acc0);
                acc1 = fmaf(xv[j].y, wv.y, acc1);
                acc0 = fmaf(xv[j].z, wv.z, acc0);
                acc1 = fmaf(xv[j].w, wv.w, acc1);
            }
        }
        float acc = acc0 + acc1;

        #pragma unroll
        for (int off = 16; off > 0; off >>= 1)
            acc += __shfl_xor_sync(0xFFFFFFFFu, acc, off);

        if (lane == 0)
            y[row] = acc + b;
    }
}

extern "C" void kernel_launch(void* const* d_in, const int* in_sizes, int n_in,
                              void* d_out, int out_size)
{
    const float* x      = (const float*)d_in[0];   // [N, H] fp32
    const int*   codes  = (const int*)  d_in[1];   // [1, H] int32
    const float* absmax = (const float*)d_in[2];   // [1, H/64] fp32
    const float* bias   = (const float*)d_in[3];   // [1] fp32
    float*       y      = (float*)d_out;           // [N, 1] fp32

    const int N = in_sizes[0] / H_DIM;             // 32768

    fp4_dequant_kernel<<<(H_DIM + 255) / 256, 256>>>(codes, absmax);
    fp4_gemv_kernel<<<GRID_CTAS, THREADS>>>(x, bias, y, N);
}

// round 14
// speedup vs baseline: 1.0480x; 1.0476x over previous
#include <cuda_runtime.h>
#include <cstdint>

// y[N] = x[N,H] @ w[H] + bias,  w[h] = FP4_TABLE[codes[h]] * absmax[h>>6]
// N = 32768, H = 4096.
//
// R13: R12 minus PDL (two consecutive container failures on the PDL kernel =
// possible hang suspect; de-risk by landing the tail change alone).
//  - half-row work quantum: 2 warps/row, 32B smem pair-combine, grid 8192.
//    Drain tail ~halves vs R8's 16KB/warp quantum.
//  - dequant pre-kernel unchanged, plain stream-ordered launch.

#define H_DIM 4096
#define THREADS 256                  // 8 warps: 4 rows/CTA, 2 warps per row
#define ROWS_PER_CTA 4

__device__ float g_w[H_DIM];         // dequantized weight scratch

__device__ __constant__ float c_fp4_tab[16] = {
    0.0f, 0.0052083333f, 0.6666667f, 1.0f, 0.3333333f, 0.5f, 0.16666667f, 0.25f,
    -0.0f, -0.0052083333f, -0.6666667f, -1.0f, -0.3333333f, -0.5f, -0.16666667f, -0.25f
};

__global__ void fp4_dequant_kernel(const int* __restrict__ codes,
                                   const float* __restrict__ absmax)
{
    int i = blockIdx.x * blockDim.x + threadIdx.x;
    if (i < H_DIM)
        g_w[i] = c_fp4_tab[codes[i] & 15] * absmax[i >> 6];
}

__global__ __launch_bounds__(THREADS)
void fp4_gemv_kernel(const float* __restrict__ x,
                     const float* __restrict__ bias,
                     float*       __restrict__ y,
                     int N)
{
    __shared__ float part[8];          // one partial per warp (32 B)

    const int warp = threadIdx.x >> 5;
    const int lane = threadIdx.x & 31;
    const int half = warp & 1;                         // which half-row
    const int row  = blockIdx.x * ROWS_PER_CTA + (warp >> 1);
    const bool live = (row < N);       // always true for N=32768; barrier-safe guard

    const size_t safe_row = live ? (size_t)row : 0;
    const float4* __restrict__ xr =
        reinterpret_cast<const float4*>(x + safe_row * H_DIM + half * (H_DIM / 2));
    const float4* __restrict__ wr =
        reinterpret_cast<const float4*>(g_w) + half * (H_DIM / 8);
    const float b = __ldg(bias);

    // Half-row = 512 float4; 16 per lane, as 2 groups of 8 (R8 body shape).
    float acc0 = 0.0f, acc1 = 0.0f;
    #pragma unroll
    for (int g = 0; g < 2; g++) {
        float4 xv[8];
        #pragma unroll
        for (int j = 0; j < 8; j++) {
            xv[j] = __ldcs(&xr[g * 256 + j * 32 + lane]);  // read-once stream
        }
        #pragma unroll
        for (int j = 0; j < 8; j++) {
            float4 wv = __ldg(&wr[g * 256 + j * 32 + lane]); // L1-resident 16KB
            acc0 = fmaf(xv[j].x, wv.x, acc0);
            acc1 = fmaf(xv[j].y, wv.y, acc1);
            acc0 = fmaf(xv[j].z, wv.z, acc0);
            acc1 = fmaf(xv[j].w, wv.w, acc1);
        }
    }
    float acc = acc0 + acc1;

    #pragma unroll
    for (int off = 16; off > 0; off >>= 1)
        acc += __shfl_xor_sync(0xFFFFFFFFu, acc, off);

    if (lane == 0) part[warp] = acc;
    __syncthreads();                   // end-of-CTA combine (no preamble cost)

    if (live && half == 0 && lane == 0)
        y[row] = part[warp] + part[warp + 1] + b;
}

extern "C" void kernel_launch(void* const* d_in, const int* in_sizes, int n_in,
                              void* d_out, int out_size)
{
    const float* x      = (const float*)d_in[0];   // [N, H] fp32
    const int*   codes  = (const int*)  d_in[1];   // [1, H] int32
    const float* absmax = (const float*)d_in[2];   // [1, H/64] fp32
    const float* bias   = (const float*)d_in[3];   // [1] fp32
    float*       y      = (float*)d_out;           // [N, 1] fp32

    const int N = in_sizes[0] / H_DIM;             // 32768

    fp4_dequant_kernel<<<(H_DIM + 255) / 256, 256>>>(codes, absmax);

    const int grid = (N + ROWS_PER_CTA - 1) / ROWS_PER_CTA;   // 8192
    fp4_gemv_kernel<<<grid, THREADS>>>(x, bias, y, N);
}